// round 17
// baseline (speedup 1.0000x reference)
#include <cuda_runtime.h>
#include <math.h>
#include <stdint.h>
#include <stddef.h>

#define N_NODES 131072
#define E_EDGES 2097152
#define B_PAIRS 4096
#define R_REL   5
#define L_LAYERS 4
#define T_STEPS 4096

// ---------------- device scratch (static globals; no runtime allocation) ----
static __device__ float g_relfeat[(size_t)N_NODES * R_REL * 32];  // 80 MB
static __device__ float g_agg[(size_t)N_NODES * 32];              // 16 MB
static __device__ float g_states[(size_t)N_NODES * 128];          // 64 MB
static __device__ int   g_cnt[(size_t)N_NODES * R_REL];           // 2.5 MB (becomes float recip)
static __device__ float g_weff[L_LAYERS * 32 * 192];              // 96 KB
static __device__ float g_z [(size_t)B_PAIRS * 256];              // 4 MB
static __device__ float g_xg[(size_t)T_STEPS * 1024];             // 16 MB
// Replicated mailboxes: cut waiters-per-L2-line (R12 showed poll traffic on
// the hot lines taxes the producers' release commits).
//   g_h1p[0..1]: layer-0 recurrence consumers (CTAs 0-15 / 16-31)
//   g_h1p[2..3]: xg2-stage consumers       (CTAs 0-15 / 16-31)
//   g_h2p[0..1]: layer-1 recurrence consumers (CTAs 0-15 / 16-31); k_head reads [0]
static __device__ unsigned long long g_h1p[4][(size_t)T_STEPS * 256];   // 32 MB
static __device__ unsigned long long g_h2p[2][(size_t)T_STEPS * 256];   // 16 MB
static __device__ unsigned long long g_xg2p[(size_t)T_STEPS * 1024];    // 32 MB

// ---------------- packed publish/poll: scalar b64 + acquire/release ---------
// PROTOCOL FROZEN — every alternative measured worse or wrong:
//  - weak b64 (.cv/.cg), v2.u32           -> rel_err ~0.3 (stale payload)
//  - pipelined multi-load poll (R12)      -> +2.4ms (poll traffic taxes producers)
//  - DSMEM bulk-copy (R10)                -> +1.6ms
//  - DSMEM scalar release stores (R15)    -> +4.1ms
//  - CTA-count / reg-shape variants       -> flat (R7/R9/R13)
__device__ __forceinline__ unsigned long long load_word(const unsigned long long* p) {
    unsigned long long w;
    asm volatile("ld.global.acquire.gpu.b64 %0, [%1];"
                 : "=l"(w) : "l"(p) : "memory");
    return w;
}
__device__ __forceinline__ float poll_word(const unsigned long long* p, unsigned tag) {
    unsigned long long w;
    do {
        asm volatile("ld.global.acquire.gpu.b64 %0, [%1];"
                     : "=l"(w) : "l"(p) : "memory");
    } while ((unsigned)(w >> 32) != tag);
    return __uint_as_float((unsigned)(w & 0xffffffffull));
}
__device__ __forceinline__ void publish_word(unsigned long long* p, float h, unsigned tag) {
    unsigned long long w = ((unsigned long long)tag << 32)
                         | (unsigned long long)__float_as_uint(h);
    asm volatile("st.global.release.gpu.b64 [%0], %1;"
                 :: "l"(p), "l"(w) : "memory");
}

// ---------------- init: zero counts ------------------------------------------
__global__ void k_init() {
    int i = blockIdx.x * blockDim.x + threadIdx.x;
    if (i < N_NODES * R_REL) g_cnt[i] = 0;
}

// ---------------- zero ALL packed tag buffers (graph-replay safe) ------------
__global__ void k_zerotags() {
    size_t i = (size_t)blockIdx.x * blockDim.x + threadIdx.x;
    if (i < (size_t)T_STEPS * 1024) g_xg2p[i] = 0ull;
    if (i < (size_t)T_STEPS * 256) {
        g_h1p[0][i] = 0ull; g_h1p[1][i] = 0ull;
        g_h1p[2][i] = 0ull; g_h1p[3][i] = 0ull;
        g_h2p[0][i] = 0ull; g_h2p[1][i] = 0ull;
    }
}

// ---------------- per-(dst,rel) edge counts ----------------------------------
__global__ void k_count(const int* __restrict__ ei, const int* __restrict__ et) {
    int e = blockIdx.x * blockDim.x + threadIdx.x;
    if (e >= E_EDGES) return;
    int dst = ei[E_EDGES + e];
    int r   = et[e];
    atomicAdd(&g_cnt[(size_t)dst * R_REL + r], 1);
}

// ---------------- convert counts -> reciprocal norms in place ----------------
__global__ void k_norm() {
    int i = blockIdx.x * blockDim.x + threadIdx.x;
    if (i >= N_NODES * R_REL) return;
    int c = g_cnt[i];
    float n = 1.0f / (float)(c < 1 ? 1 : c);
    ((float*)g_cnt)[i] = n;
}

// ---------------- effective relation weights ---------------------------------
__global__ void k_weff(const float* __restrict__ basis,
                       const float* __restrict__ comp,
                       const float* __restrict__ root) {
    int idx = blockIdx.x * blockDim.x + threadIdx.x;
    if (idx >= L_LAYERS * 32 * 192) return;
    int l = idx / (32 * 192);
    int rem = idx % (32 * 192);
    int i = rem / 192;
    int o = rem % 192;
    int r = o / 32, j = o % 32;
    float v;
    if (r < R_REL) {
        v = 0.f;
        #pragma unroll
        for (int b = 0; b < 4; b++)
            v += comp[(l * R_REL + r) * 4 + b] * basis[(((size_t)l * 4 + b) * 32 + i) * 32 + j];
    } else {
        v = root[((size_t)l * 32 + i) * 32 + j];
    }
    g_weff[idx] = v;
}

// ---------------- node transform (fused tanh of previous layer) --------------
__global__ void k_transform(const float* __restrict__ x,
                            const float* __restrict__ cbias, int l) {
    __shared__ __align__(16) float hs[32][32];
    int n0 = blockIdx.x * 32;
    int tid = threadIdx.x;  // 0..191

    for (int i = tid; i < 1024; i += 192) {
        int m = i >> 5, c = i & 31;
        float v;
        if (l == 0) {
            v = x[(size_t)(n0 + m) * 32 + c];
        } else {
            v = tanhf(g_agg[(size_t)(n0 + m) * 32 + c]);
            g_states[(size_t)(n0 + m) * 128 + (l - 1) * 32 + c] = v;
        }
        hs[m][c] = v;
    }
    float wreg[32];
    const float* W = g_weff + l * 32 * 192;
    #pragma unroll
    for (int i = 0; i < 32; i++) wreg[i] = W[i * 192 + tid];
    __syncthreads();

    int r = tid / 32, o = tid % 32;
    float bias = (r == 5) ? cbias[o] : 0.f;

    for (int m = 0; m < 32; m++) {
        const float4* hp = (const float4*)hs[m];
        float acc = 0.f;
        #pragma unroll
        for (int i4 = 0; i4 < 8; i4++) {
            float4 h4 = hp[i4];
            acc += h4.x * wreg[i4 * 4 + 0];
            acc += h4.y * wreg[i4 * 4 + 1];
            acc += h4.z * wreg[i4 * 4 + 2];
            acc += h4.w * wreg[i4 * 4 + 3];
        }
        if (r < R_REL)
            g_relfeat[((size_t)(n0 + m) * R_REL + r) * 32 + o] = acc;
        else
            g_agg[(size_t)(n0 + m) * 32 + o] = acc + bias;
    }
}

// ---------------- edge aggregation: 8 lanes/edge, vector reductions ----------
__global__ void k_edge(const int* __restrict__ ei, const int* __restrict__ et) {
    int gid = blockIdx.x * blockDim.x + threadIdx.x;
    int e = gid >> 3;
    int q = gid & 7;
    if (e >= E_EDGES) return;
    int src = ei[e];
    int dst = ei[E_EDGES + e];
    int r   = et[e];
    float norm = ((const float*)g_cnt)[(size_t)dst * R_REL + r];
    float4 v = *(const float4*)&g_relfeat[((size_t)src * R_REL + r) * 32 + q * 4];
    float* p = &g_agg[(size_t)dst * 32 + q * 4];
    asm volatile("red.global.add.v4.f32 [%0], {%1,%2,%3,%4};"
                 :: "l"(p), "f"(v.x * norm), "f"(v.y * norm),
                    "f"(v.z * norm), "f"(v.w * norm)
                 : "memory");
}

// ---------------- tanh into concat states (final layer only) -----------------
__global__ void k_tanh(int l) {
    int i = blockIdx.x * blockDim.x + threadIdx.x;
    if (i >= N_NODES * 32) return;
    int n = i >> 5, o = i & 31;
    g_states[(size_t)n * 128 + l * 32 + o] = tanhf(g_agg[i]);
}

// ---------------- gather z = [states[user], states[item]] --------------------
__global__ void k_gather(const int* __restrict__ ui, const int* __restrict__ vi) {
    int i = blockIdx.x * blockDim.x + threadIdx.x;
    if (i >= B_PAIRS * 256) return;
    int b = i >> 8, o = i & 255;
    int node = (o < 128) ? ui[b] : vi[b];
    g_z[i] = g_states[(size_t)node * 128 + (o & 127)];
}

// ---------------- x-gates GEMM for layer 0 ------------------------------------
__global__ void __launch_bounds__(256)
k_xg(const float* __restrict__ wih, const float* __restrict__ bih,
     const float* __restrict__ bhh) {
    __shared__ __align__(16) float As[32][65];
    __shared__ __align__(16) float Bs[32][65];
    int tid = threadIdx.x;
    int m0 = blockIdx.y * 64, n0 = blockIdx.x * 64;
    int tm = tid >> 4, tn = tid & 15;
    float acc[4][4];
    #pragma unroll
    for (int u = 0; u < 4; u++)
        #pragma unroll
        for (int v = 0; v < 4; v++) acc[u][v] = 0.f;

    for (int k0 = 0; k0 < 256; k0 += 32) {
        for (int i = tid; i < 512; i += 256) {
            int mm = i >> 3, kq = i & 7;
            float4 v = *(const float4*)&g_z[(size_t)(m0 + mm) * 256 + k0 + kq * 4];
            As[kq * 4 + 0][mm] = v.x; As[kq * 4 + 1][mm] = v.y;
            As[kq * 4 + 2][mm] = v.z; As[kq * 4 + 3][mm] = v.w;
        }
        for (int i = tid; i < 512; i += 256) {
            int nn = i >> 3, kq = i & 7;
            float4 v = *(const float4*)&wih[(size_t)(n0 + nn) * 256 + k0 + kq * 4];
            Bs[kq * 4 + 0][nn] = v.x; Bs[kq * 4 + 1][nn] = v.y;
            Bs[kq * 4 + 2][nn] = v.z; Bs[kq * 4 + 3][nn] = v.w;
        }
        __syncthreads();
        #pragma unroll
        for (int kk = 0; kk < 32; kk++) {
            float a[4], b[4];
            #pragma unroll
            for (int u = 0; u < 4; u++) { a[u] = As[kk][tm * 4 + u]; b[u] = Bs[kk][tn * 4 + u]; }
            #pragma unroll
            for (int u = 0; u < 4; u++)
                #pragma unroll
                for (int v = 0; v < 4; v++) acc[u][v] += a[u] * b[v];
        }
        __syncthreads();
    }
    #pragma unroll
    for (int u = 0; u < 4; u++)
        #pragma unroll
        for (int v = 0; v < 4; v++) {
            int rr = n0 + tn * 4 + v;
            g_xg[(size_t)(m0 + tm * 4 + u) * 1024 + rr] = acc[u][v] + bih[rr] + bhh[rr];
        }
}

// ---------------- persistent 2-layer LSTM scan + xg2 stage -------------------
// 96 CTAs x 256 threads.
//   blocks 0..31  : layer-0 recurrence (W_hh0 in regs, x-gates from g_xg)
//   blocks 32..63 : layer-1 recurrence (W_hh1 in regs, x-gates from g_xg2p)
//   blocks 64..95 : xg2 stage (32 CTAs, 32 rows, 32 w-regs)
// Mailbox replication: consumers split across replicas (16 waiters/word);
// producers publish via ONE predicated store instruction with 2-4 active
// lanes (cst/h made warp-uniform — same instruction count as lane-0 version).
__global__ void __launch_bounds__(256, 1)
k_scan(const float* __restrict__ wih_g, const float* __restrict__ whh_g,
       const float* __restrict__ bih, const float* __restrict__ bhh) {
    int blk = blockIdx.x;
    int tid = threadIdx.x;

    if (blk >= 64) {
        // ---------------- xg2 GEMV stage ----------------
        int c = blk - 64;                 // 0..31
        int rowc = c * 32 + (tid >> 3);   // gate row 0..1023
        int sub = tid & 7;                // 32-col slice
        const unsigned long long* h1src = g_h1p[2 + (c >> 4)];
        float wr[32];
        {
            const float* W = wih_g + (size_t)262144 + (size_t)rowc * 256 + sub * 32;
            #pragma unroll
            for (int q = 0; q < 32; q++) wr[q] = W[q];
        }
        float bias = (sub == 0) ? (bih[1024 + rowc] + bhh[1024 + rowc]) : 0.f;
        __shared__ __align__(16) float h1s[2][288];

        #pragma unroll 1
        for (int t = 0; t < T_STEPS; t++) {
            int buf = t & 1;
            int pos = (tid >> 5) * 36 + (tid & 31);
            h1s[buf][pos] = poll_word(&h1src[(size_t)t * 256 + tid], (unsigned)(t + 1));
            __syncthreads();

            float a0 = 0.f, a1 = 0.f, a2 = 0.f, a3 = 0.f;
            const float4* hp = (const float4*)&h1s[buf][sub * 36];
            #pragma unroll
            for (int q = 0; q < 8; q++) {
                float4 h4 = hp[q];
                a0 += wr[4*q]   * h4.x;
                a1 += wr[4*q+1] * h4.y;
                a2 += wr[4*q+2] * h4.z;
                a3 += wr[4*q+3] * h4.w;
            }
            float acc = (a0 + a1) + (a2 + a3);
            acc += __shfl_xor_sync(0xffffffffu, acc, 1);
            acc += __shfl_xor_sync(0xffffffffu, acc, 2);
            acc += __shfl_xor_sync(0xffffffffu, acc, 4);
            if (sub == 0)
                publish_word(&g_xg2p[(size_t)t * 1024 + rowc], acc + bias,
                             (unsigned)(t + 1));
        }
        return;
    }

    // ---------------- recurrence layers ----------------
    int layer = blk >> 5;
    int k = blk & 31;
    int w = tid >> 5, lane = tid & 31;
    int p = lane >> 3, s = lane & 7;
    int j = k * 8 + w;           // h index 0..255
    int row = p * 256 + j;       // gate row 0..1023

    float whh[32];
    {
        const float* WhhP = whh_g + (size_t)layer * 262144 + (size_t)row * 256 + s * 32;
        #pragma unroll
        for (int c = 0; c < 32; c++) whh[c] = WhhP[c];
    }

    // consumer replica + per-lane publish base
    const unsigned long long* inp =
        (layer == 0) ? g_h1p[k >> 4] : g_h2p[k >> 4];
    int nrep = (layer == 0) ? 4 : 2;
    unsigned long long* pub_base =
        (layer == 0) ? g_h1p[lane & 3] : g_h2p[lane & 1];

    __shared__ __align__(16) float hA[2][288];   // own-layer h(t-1)
    float cst = 0.f;   // warp-uniform (all lanes compute identically)

    #pragma unroll 1
    for (int t = 0; t < T_STEPS; t++) {
        int buf = t & 1;
        float xg = 0.f;
        unsigned long long wx = 0ull;
        const unsigned long long* xp2 = 0;

        if (s == 0) {
            if (layer == 0) {
                xg = __ldg(&g_xg[(size_t)t * 1024 + row]);
            } else {
                // speculative xg2 load, issued BEFORE the recurrence spin
                xp2 = &g_xg2p[(size_t)t * 1024 + row];
                wx = load_word(xp2);
            }
        }

        // ---- recurrence spin: own-layer h(t-1) ----
        int pos = (tid >> 5) * 36 + (tid & 31);
        if (t > 0)
            hA[buf][pos] = poll_word(&inp[(size_t)(t - 1) * 256 + tid], (unsigned)t);
        __syncthreads();

        // ---- verify speculative xg2 (hits first try in steady state) ----
        if (layer == 1 && s == 0) {
            while ((unsigned)(wx >> 32) != (unsigned)(t + 1)) wx = load_word(xp2);
            xg = __uint_as_float((unsigned)(wx & 0xffffffffull));
        }

        // ---- gate dot products: 4 independent accumulator chains ----
        float a0 = 0.f, a1 = 0.f, a2 = 0.f, a3 = 0.f;
        if (t > 0) {
            const float4* hp = (const float4*)&hA[buf][s * 36];
            #pragma unroll
            for (int q = 0; q < 8; q++) {
                float4 h4 = hp[q];
                a0 += whh[4*q]   * h4.x;
                a1 += whh[4*q+1] * h4.y;
                a2 += whh[4*q+2] * h4.z;
                a3 += whh[4*q+3] * h4.w;
            }
        }
        float acc = (a0 + a1) + (a2 + a3);
        acc += __shfl_xor_sync(0xffffffffu, acc, 4);
        acc += __shfl_xor_sync(0xffffffffu, acc, 2);
        acc += __shfl_xor_sync(0xffffffffu, acc, 1);

        float gact = 0.f;
        if (s == 0) {
            float gv = acc + xg;
            gact = (p == 2) ? tanhf(gv) : __fdividef(1.f, 1.f + __expf(-gv));
        }
        float gi = __shfl_sync(0xffffffffu, gact, 0);
        float gf = __shfl_sync(0xffffffffu, gact, 8);
        float gg = __shfl_sync(0xffffffffu, gact, 16);
        float go = __shfl_sync(0xffffffffu, gact, 24);

        // warp-uniform cell update (same instruction count as lane-0-only)
        cst = gf * cst + gi * gg;
        float h = go * tanhf(cst);
        if (lane < nrep)
            publish_word(&pub_base[(size_t)t * 256 + j], h, (unsigned)(t + 1));
    }
}

// ---------------- final MLP head ----------------------------------------------
__global__ void k_head(const float* __restrict__ l1w, const float* __restrict__ l1b,
                       const float* __restrict__ l2w, const float* __restrict__ l2b,
                       float* __restrict__ out) {
    int b = blockIdx.x;
    int tid = threadIdx.x;  // 256 threads
    int w = tid >> 5, lane = tid & 31;
    __shared__ __align__(16) float hs[256];
    __shared__ float rs[128];
    __shared__ float part[8];

    hs[tid] = __uint_as_float((unsigned)(g_h2p[0][(size_t)b * 256 + tid] & 0xffffffffull));
    __syncthreads();

    for (int q = 0; q < 16; q++) {
        int jrow = w * 16 + q;
        const float4* wp = (const float4*)(l1w + (size_t)jrow * 256 + lane * 8);
        float4 wa = wp[0], wb = wp[1];
        const float4* hp = (const float4*)(hs + lane * 8);
        float4 haa = hp[0], hbb = hp[1];
        float acc = wa.x * haa.x + wa.y * haa.y + wa.z * haa.z + wa.w * haa.w
                  + wb.x * hbb.x + wb.y * hbb.y + wb.z * hbb.z + wb.w * hbb.w;
        #pragma unroll
        for (int sft = 16; sft > 0; sft >>= 1)
            acc += __shfl_xor_sync(0xffffffffu, acc, sft);
        if (lane == 0) rs[jrow] = fmaxf(acc + l1b[jrow], 0.f);
    }
    __syncthreads();

    float v = (tid < 128) ? rs[tid] * l2w[tid] : 0.f;
    #pragma unroll
    for (int sft = 16; sft > 0; sft >>= 1)
        v += __shfl_xor_sync(0xffffffffu, v, sft);
    if (lane == 0) part[w] = v;
    __syncthreads();
    if (tid == 0) {
        float sum = 0.f;
        #pragma unroll
        for (int i = 0; i < 8; i++) sum += part[i];
        out[b] = sum + l2b[0];
    }
}

// ---------------- launch --------------------------------------------------------
extern "C" void kernel_launch(void* const* d_in, const int* in_sizes, int n_in,
                              void* d_out, int out_size) {
    const float* x     = (const float*)d_in[0];
    const int*   ei    = (const int*)  d_in[1];
    const int*   et    = (const int*)  d_in[2];
    const int*   ui    = (const int*)  d_in[3];
    const int*   vi    = (const int*)  d_in[4];
    const float* basis = (const float*)d_in[5];
    const float* comp  = (const float*)d_in[6];
    const float* root  = (const float*)d_in[7];
    const float* cbias = (const float*)d_in[8];
    const float* w_ih  = (const float*)d_in[9];
    const float* w_hh  = (const float*)d_in[10];
    const float* b_ih  = (const float*)d_in[11];
    const float* b_hh  = (const float*)d_in[12];
    const float* l1w   = (const float*)d_in[13];
    const float* l1b   = (const float*)d_in[14];
    const float* l2w   = (const float*)d_in[15];
    const float* l2b   = (const float*)d_in[16];
    float* out = (float*)d_out;

    k_init<<<(N_NODES * R_REL + 255) / 256, 256>>>();
    k_zerotags<<<(T_STEPS * 1024 + 255) / 256, 256>>>();
    k_count<<<(E_EDGES + 255) / 256, 256>>>(ei, et);
    k_norm<<<(N_NODES * R_REL + 255) / 256, 256>>>();
    k_weff<<<(L_LAYERS * 32 * 192 + 255) / 256, 256>>>(basis, comp, root);

    for (int l = 0; l < L_LAYERS; l++) {
        k_transform<<<N_NODES / 32, 192>>>(x, cbias + l * 32, l);
        k_edge<<<((size_t)E_EDGES * 8) / 256, 256>>>(ei, et);
    }
    k_tanh<<<(N_NODES * 32) / 256, 256>>>(L_LAYERS - 1);

    k_gather<<<(B_PAIRS * 256) / 256, 256>>>(ui, vi);
    k_xg<<<dim3(16, 64), 256>>>(w_ih, b_ih, b_hh);
    k_scan<<<96, 256>>>(w_ih, w_hh, b_ih, b_hh);
    k_head<<<B_PAIRS, 256>>>(l1w, l1b, l2w, l2b, out);
}